// round 12
// baseline (speedup 1.0000x reference)
#include <cuda_runtime.h>
#include <cstdint>

// Twist2Mat (Rodrigues): twist [B,R,3] f32 -> rot [B,R,3,3] f32
// N = B*R = 8,388,608. Memory-bound: 384 MB streaming (96 read / 288 write).
//
// R1..R11 history: coalescing via warp-private smem staging + TMA bulk stores
// brought 166us -> 63.55us; DRAM pinned ~74% (5.85 TB/s) across occ 37-79%.
// R12: PERSISTENT grid-stride warps. 304 blocks (2/SM), each warp loops over
//      ~27 chunks of 128 elems with double-buffered s_out: bulk store of
//      chunk i overlaps load+compute of chunk i+1 in the same warp
//      (wait_group.read 1 gates smem buffer reuse). Removes 8k block
//      entry/exits and wave-transition bubbles.

#ifndef TPB
#define TPB 256
#endif
#define WARPS (TPB / 32)
#define CHUNK 128                  // elements per chunk per warp
#define BLOCKS 304                 // 2 blocks per SM on 152-SM GB300

__device__ __forceinline__ void rodrigues9(float x, float y, float z, float* __restrict__ r)
{
    float n2    = fmaf(x, x, fmaf(y, y, z * z));
    float theta = fmaxf(sqrtf(n2), 1e-5f);
    float inv   = __fdividef(1.0f, theta);
    float a0 = x * inv, a1 = y * inv, a2 = z * inv;

    float s, c;
    __sincosf(theta, &s, &c);
    float k = 1.0f - c;

    // R = c*I + s*[a]_x + k*(a a^T)
    float ka0 = k * a0, ka1 = k * a1;
    float sa0 = s * a0, sa1 = s * a1, sa2 = s * a2;

    r[0] = fmaf(ka0, a0, c);
    r[1] = fmaf(ka0, a1, -sa2);
    r[2] = fmaf(ka0, a2,  sa1);
    r[3] = fmaf(ka0, a1,  sa2);
    r[4] = fmaf(ka1, a1, c);
    r[5] = fmaf(ka1, a2, -sa0);
    r[6] = fmaf(ka0, a2, -sa1);
    r[7] = fmaf(ka1, a2,  sa0);
    r[8] = fmaf(k * a2, a2, c);
}

__global__ __launch_bounds__(TPB)
void twist2mat_persist_kernel(const float4* __restrict__ in4,
                              float4* __restrict__ out4,
                              int n_elems)
{
    __shared__ float s_in [WARPS][CHUNK * 3];                      // 1536 B / warp
    __shared__ __align__(16) float s_out[WARPS][2][CHUNK * 9];     // 2 x 4608 B / warp

    const int lane = threadIdx.x & 31;
    const int wrp  = threadIdx.x >> 5;
    const int wgid = blockIdx.x * WARPS + wrp;          // global warp id
    const int nwarps = BLOCKS * WARPS;

    const int n_chunks = (n_elems + CHUNK - 1) / CHUNK; // 65536 for this shape

    int it = 0;                                          // this warp's iteration count
    for (int c = wgid; c < n_chunks; c += nwarps, it++) {
        const long long cstart = (long long)c * CHUNK;
        const float4* gin  = in4  + cstart / 4 * 3;
        float4*       gout = out4 + cstart / 4 * 9;
        const bool full = (cstart + CHUNK <= n_elems);
        const int buf = it & 1;

        // ---- batched coalesced load: 96 float4 per warp (3 per lane) ----
        // Overlaps with the previous chunk's bulk store (still in flight).
        if (full) {
            float4* s = (float4*)s_in[wrp];
#pragma unroll
            for (int j = 0; j < 3; j++)
                s[lane + 32 * j] = __ldcs(gin + lane + 32 * j);
        } else {
            const float* gf = (const float*)gin;
            int vf = (int)(n_elems - cstart) * 3;
            for (int i = lane; i < CHUNK * 3; i += 32)
                s_in[wrp][i] = (i < vf) ? gf[i] : 1.0f;   // pad, never stored
        }

        // ---- gate reuse of s_out[buf]: the group committed at it-2 (same
        // buffer) must have finished READING smem. Groups retire in order,
        // so "<=1 pending" suffices. ----
        if (it >= 2) {
            if (lane == 0)
                asm volatile("cp.async.bulk.wait_group.read 1;" ::: "memory");
        }
        __syncwarp();   // orders: loads visible, wait done, before compute

        // ---- compute 4 tiles of 32 into contiguous 4608B buffer ----
        float* sob = s_out[wrp][buf];
#pragma unroll
        for (int t = 0; t < 4; t++) {
            const float* si = s_in[wrp] + t * 96;
            float x = si[3 * lane + 0];
            float y = si[3 * lane + 1];
            float z = si[3 * lane + 2];
            float r[9];
            rodrigues9(x, y, z, r);
            float* so = sob + t * 288;
#pragma unroll
            for (int i = 0; i < 9; i++)
                so[9 * lane + i] = r[i];               // stride-9 STS: conflict-free
        }
        __syncwarp();

        if (full) {
            // ---- single TMA bulk store: 4608 contiguous bytes, async ----
            if (lane == 0) {
                asm volatile("fence.proxy.async.shared::cta;" ::: "memory");
                uint32_t src = (uint32_t)__cvta_generic_to_shared(sob);
                asm volatile(
                    "cp.async.bulk.global.shared::cta.bulk_group [%0], [%1], %2;"
                    :: "l"((void*)gout), "r"(src), "n"(4608) : "memory");
                asm volatile("cp.async.bulk.commit_group;" ::: "memory");
            }
        } else {
            // scalar-safe tail store (not hit for this shape)
            float* gf = (float*)gout;
            int vf = (int)(n_elems - cstart) * 9;
            for (int i = lane; i < vf; i += 32)
                gf[i] = sob[i];
            if (lane == 0) {  // keep group accounting uniform
                asm volatile("cp.async.bulk.commit_group;" ::: "memory");
            }
            __syncwarp();
        }
    }

    // Drain: all bulk stores must finish reading smem before CTA retires.
    if (lane == 0)
        asm volatile("cp.async.bulk.wait_group.read 0;" ::: "memory");
}

extern "C" void kernel_launch(void* const* d_in, const int* in_sizes, int n_in,
                              void* d_out, int out_size)
{
    const float* twist = (const float*)d_in[0];
    float* out = (float*)d_out;

    int n_elems = in_sizes[0] / 3;   // 8,388,608

    twist2mat_persist_kernel<<<BLOCKS, TPB>>>((const float4*)twist, (float4*)out, n_elems);
}

// round 13
// speedup vs baseline: 1.0640x; 1.0640x over previous
#include <cuda_runtime.h>
#include <cstdint>

// Twist2Mat (Rodrigues): twist [B,R,3] f32 -> rot [B,R,3,3] f32
// N = B*R = 8,388,608. Memory-bound: 384 MB streaming (96 read / 288 write).
//
// Final form (R13 = R9 + read-only exit drain). History:
// R1: strided per-thread stores -> 9x L1 wf amplification (166us).
// R2: block smem staging, coalesced I/O (66.3us).
// R3: warp-private tiles + __ldcs/__stcs (63.9us).
// R4/R5: prefetch / read-MLP batching — neutral.
// R6: TMA bulk stores (63.9us harness, 58.7us profile).
// R7: TMA bulk loads — neutral-negative; LDG loads kept.
// R9: paired 2304B TMA stores — BEST (63.55us harness, 58.6us profile, DRAM 74%).
// R10/R11: single 4608B store — neutral.
// R12: persistent 304-block grid — REGRESSED (occ 24%, read stream starved).
// Conclusion: pinned at ~5.85 TB/s, the HBM mixed-stream (1R:3W) ceiling.
// R13 trims the warp-exit drain to smem-read completion only.

#ifndef TPB
#define TPB 256
#endif
#define WARPS (TPB / 32)
#define TILES 4            // 32-element tiles per warp => 128 elems/warp

__device__ __forceinline__ void rodrigues9(float x, float y, float z, float* __restrict__ r)
{
    float n2    = fmaf(x, x, fmaf(y, y, z * z));
    float theta = fmaxf(sqrtf(n2), 1e-5f);
    float inv   = __fdividef(1.0f, theta);
    float a0 = x * inv, a1 = y * inv, a2 = z * inv;

    float s, c;
    __sincosf(theta, &s, &c);
    float k = 1.0f - c;

    // R = c*I + s*[a]_x + k*(a a^T)
    float ka0 = k * a0, ka1 = k * a1;
    float sa0 = s * a0, sa1 = s * a1, sa2 = s * a2;

    r[0] = fmaf(ka0, a0, c);
    r[1] = fmaf(ka0, a1, -sa2);
    r[2] = fmaf(ka0, a2,  sa1);
    r[3] = fmaf(ka0, a1,  sa2);
    r[4] = fmaf(ka1, a1, c);
    r[5] = fmaf(ka1, a2, -sa0);
    r[6] = fmaf(ka0, a2, -sa1);
    r[7] = fmaf(ka1, a2,  sa0);
    r[8] = fmaf(k * a2, a2, c);
}

__global__ __launch_bounds__(TPB)
void twist2mat_final_kernel(const float4* __restrict__ in4,
                            float4* __restrict__ out4,
                            int n_elems)
{
    __shared__ float s_in [WARPS][TILES * 96];                 // 1536 B / warp
    __shared__ __align__(16) float s_out[WARPS][2][576];       // 2 x 2304 B / warp

    const int lane = threadIdx.x & 31;
    const int wrp  = threadIdx.x >> 5;
    const long long wstart = ((long long)blockIdx.x * WARPS + wrp) * (32 * TILES);
    if (wstart >= n_elems) return;

    const float4* gin  = in4  + wstart / 4 * 3;   // wstart*3/4
    float4*       gout = out4 + wstart / 4 * 9;   // wstart*9/4

    const bool warp_full = (wstart + 32 * TILES <= n_elems);

    // ---- batched coalesced load: 96 float4 per warp (3 per lane) ----
    if (warp_full) {
        float4* s = (float4*)s_in[wrp];
#pragma unroll
        for (int j = 0; j < 3; j++)
            s[lane + 32 * j] = __ldcs(gin + lane + 32 * j);
    } else {
        const float* gf = (const float*)gin;
        int vf = (int)(n_elems - wstart) * 3;
        for (int i = lane; i < TILES * 96; i += 32)
            s_in[wrp][i] = (i < vf) ? gf[i] : 1.0f;   // pad, never stored
    }
    __syncwarp();

    if (warp_full) {
#pragma unroll
        for (int p = 0; p < TILES / 2; p++) {
            // ---- compute two tiles into one contiguous 2304B buffer ----
            float* sop = s_out[wrp][p];
#pragma unroll
            for (int sub = 0; sub < 2; sub++) {
                const int t = 2 * p + sub;
                const float* si = s_in[wrp] + t * 96;
                float x = si[3 * lane + 0];
                float y = si[3 * lane + 1];
                float z = si[3 * lane + 2];
                float r[9];
                rodrigues9(x, y, z, r);
                float* so = sop + sub * 288;
#pragma unroll
                for (int i = 0; i < 9; i++)
                    so[9 * lane + i] = r[i];          // stride-9 STS: conflict-free
            }
            __syncwarp();

            // ---- one TMA bulk store per pair: 2304 contiguous bytes ----
            if (lane == 0) {
                asm volatile("fence.proxy.async.shared::cta;" ::: "memory");
                uint32_t src = (uint32_t)__cvta_generic_to_shared(sop);
                void* dst = (void*)(gout + p * 144);
                asm volatile(
                    "cp.async.bulk.global.shared::cta.bulk_group [%0], [%1], %2;"
                    :: "l"(dst), "r"(src), "n"(2304) : "memory");
                asm volatile("cp.async.bulk.commit_group;" ::: "memory");
            }
            // no mid-loop wait: each buffer is written exactly once
        }
        // Exit drain: only require the TMA engine to have finished READING
        // smem (safe for smem reuse after CTA retire); do NOT wait for global
        // write visibility -> warps retire without the DRAM write-latency tail.
        if (lane == 0)
            asm volatile("cp.async.bulk.wait_group.read 0;" ::: "memory");
    } else {
        // ---- scalar-safe tail path (not hit for this shape) ----
        for (int t = 0; t < TILES; t++) {
            const long long tbase = wstart + 32LL * t;
            if (tbase >= n_elems) break;
            const float* si = s_in[wrp] + t * 96;
            float r[9];
            rodrigues9(si[3 * lane], si[3 * lane + 1], si[3 * lane + 2], r);
            float* so = s_out[wrp][0];
#pragma unroll
            for (int i = 0; i < 9; i++)
                so[9 * lane + i] = r[i];
            __syncwarp();
            float* gf = (float*)(gout + t * 72);
            long long ve = n_elems - tbase;
            int vf = (int)((ve < 32 ? ve : 32) * 9);
            for (int i = lane; i < vf; i += 32)
                gf[i] = so[i];
            __syncwarp();
        }
    }
}

extern "C" void kernel_launch(void* const* d_in, const int* in_sizes, int n_in,
                              void* d_out, int out_size)
{
    const float* twist = (const float*)d_in[0];
    float* out = (float*)d_out;

    int n_elems = in_sizes[0] / 3;                       // 8,388,608
    long long per_block = (long long)WARPS * 32 * TILES; // 1024
    int blocks = (int)((n_elems + per_block - 1) / per_block);

    twist2mat_final_kernel<<<blocks, TPB>>>((const float4*)twist, (float4*)out, n_elems);
}

// round 14
// speedup vs baseline: 1.0710x; 1.0065x over previous
#include <cuda_runtime.h>
#include <cstdint>

// Twist2Mat (Rodrigues): twist [B,R,3] f32 -> rot [B,R,3,3] f32
// N = B*R = 8,388,608. Memory-bound: 384 MB streaming (96 read / 288 write).
//
// History: R1 166us -> R2 66.3 (smem staging) -> R3 63.9 (warp tiles + ldcs)
// -> R6 TMA stores (58.7 profile) -> R9 paired 2304B TMA stores = BEST
// (63.55 harness / 58.6 profile, DRAM 74%). R4/5/7/10/11/13 neutral,
// R12 persistent regressed. Plateau ~5.85 TB/s = HBM 1R:3W ceiling.
// R14: R9 + L2::evict_first cache-hint on the TMA write stream so write
// lines leave L2 promptly (smoother writeback, less read/write thrash).

#ifndef TPB
#define TPB 256
#endif
#define WARPS (TPB / 32)
#define TILES 4            // 32-element tiles per warp => 128 elems/warp

__device__ __forceinline__ void rodrigues9(float x, float y, float z, float* __restrict__ r)
{
    float n2    = fmaf(x, x, fmaf(y, y, z * z));
    float theta = fmaxf(sqrtf(n2), 1e-5f);
    float inv   = __fdividef(1.0f, theta);
    float a0 = x * inv, a1 = y * inv, a2 = z * inv;

    float s, c;
    __sincosf(theta, &s, &c);
    float k = 1.0f - c;

    // R = c*I + s*[a]_x + k*(a a^T)
    float ka0 = k * a0, ka1 = k * a1;
    float sa0 = s * a0, sa1 = s * a1, sa2 = s * a2;

    r[0] = fmaf(ka0, a0, c);
    r[1] = fmaf(ka0, a1, -sa2);
    r[2] = fmaf(ka0, a2,  sa1);
    r[3] = fmaf(ka0, a1,  sa2);
    r[4] = fmaf(ka1, a1, c);
    r[5] = fmaf(ka1, a2, -sa0);
    r[6] = fmaf(ka0, a2, -sa1);
    r[7] = fmaf(ka1, a2,  sa0);
    r[8] = fmaf(k * a2, a2, c);
}

__global__ __launch_bounds__(TPB)
void twist2mat_r14_kernel(const float4* __restrict__ in4,
                          float4* __restrict__ out4,
                          int n_elems)
{
    __shared__ float s_in [WARPS][TILES * 96];                 // 1536 B / warp
    __shared__ __align__(16) float s_out[WARPS][2][576];       // 2 x 2304 B / warp

    const int lane = threadIdx.x & 31;
    const int wrp  = threadIdx.x >> 5;
    const long long wstart = ((long long)blockIdx.x * WARPS + wrp) * (32 * TILES);
    if (wstart >= n_elems) return;

    const float4* gin  = in4  + wstart / 4 * 3;   // wstart*3/4
    float4*       gout = out4 + wstart / 4 * 9;   // wstart*9/4

    const bool warp_full = (wstart + 32 * TILES <= n_elems);

    // ---- batched coalesced load: 96 float4 per warp (3 per lane) ----
    if (warp_full) {
        float4* s = (float4*)s_in[wrp];
#pragma unroll
        for (int j = 0; j < 3; j++)
            s[lane + 32 * j] = __ldcs(gin + lane + 32 * j);
    } else {
        const float* gf = (const float*)gin;
        int vf = (int)(n_elems - wstart) * 3;
        for (int i = lane; i < TILES * 96; i += 32)
            s_in[wrp][i] = (i < vf) ? gf[i] : 1.0f;   // pad, never stored
    }
    __syncwarp();

    if (warp_full) {
        // evict_first policy for the streaming write lines
        uint64_t pol;
        asm volatile("createpolicy.fractional.L2::evict_first.b64 %0, 1.0;" : "=l"(pol));

#pragma unroll
        for (int p = 0; p < TILES / 2; p++) {
            // ---- compute two tiles into one contiguous 2304B buffer ----
            float* sop = s_out[wrp][p];
#pragma unroll
            for (int sub = 0; sub < 2; sub++) {
                const int t = 2 * p + sub;
                const float* si = s_in[wrp] + t * 96;
                float x = si[3 * lane + 0];
                float y = si[3 * lane + 1];
                float z = si[3 * lane + 2];
                float r[9];
                rodrigues9(x, y, z, r);
                float* so = sop + sub * 288;
#pragma unroll
                for (int i = 0; i < 9; i++)
                    so[9 * lane + i] = r[i];          // stride-9 STS: conflict-free
            }
            __syncwarp();

            // ---- one TMA bulk store per pair: 2304 B, evict_first hint ----
            if (lane == 0) {
                asm volatile("fence.proxy.async.shared::cta;" ::: "memory");
                uint32_t src = (uint32_t)__cvta_generic_to_shared(sop);
                void* dst = (void*)(gout + p * 144);
                asm volatile(
                    "cp.async.bulk.global.shared::cta.bulk_group.L2::cache_hint "
                    "[%0], [%1], %2, %3;"
                    :: "l"(dst), "r"(src), "n"(2304), "l"(pol) : "memory");
                asm volatile("cp.async.bulk.commit_group;" ::: "memory");
            }
            // no mid-loop wait: each buffer is written exactly once
        }
        // Exit drain: smem-read completion only (safe for CTA retire).
        if (lane == 0)
            asm volatile("cp.async.bulk.wait_group.read 0;" ::: "memory");
    } else {
        // ---- scalar-safe tail path (not hit for this shape) ----
        for (int t = 0; t < TILES; t++) {
            const long long tbase = wstart + 32LL * t;
            if (tbase >= n_elems) break;
            const float* si = s_in[wrp] + t * 96;
            float r[9];
            rodrigues9(si[3 * lane], si[3 * lane + 1], si[3 * lane + 2], r);
            float* so = s_out[wrp][0];
#pragma unroll
            for (int i = 0; i < 9; i++)
                so[9 * lane + i] = r[i];
            __syncwarp();
            float* gf = (float*)(gout + t * 72);
            long long ve = n_elems - tbase;
            int vf = (int)((ve < 32 ? ve : 32) * 9);
            for (int i = lane; i < vf; i += 32)
                gf[i] = so[i];
            __syncwarp();
        }
    }
}

extern "C" void kernel_launch(void* const* d_in, const int* in_sizes, int n_in,
                              void* d_out, int out_size)
{
    const float* twist = (const float*)d_in[0];
    float* out = (float*)d_out;

    int n_elems = in_sizes[0] / 3;                       // 8,388,608
    long long per_block = (long long)WARPS * 32 * TILES; // 1024
    int blocks = (int)((n_elems + per_block - 1) / per_block);

    twist2mat_r14_kernel<<<blocks, TPB>>>((const float4*)twist, (float4*)out, n_elems);
}